// round 2
// baseline (speedup 1.0000x reference)
#include <cuda_runtime.h>
#include <math.h>

#define DIM 64
#define N_MAX 100000
#define E_MAX 1200000

// Scratch (static device globals — no allocation allowed)
__device__ float g_h[N_MAX * DIM];      // h = x @ W
__device__ float g_acc[N_MAX * DIM];    // unnormalized weighted sums
__device__ float g_as[N_MAX];
__device__ float g_ad[N_MAX];
__device__ float g_emax[N_MAX];
__device__ float g_denom[N_MAX];
__device__ float g_e[E_MAX + N_MAX];    // per-edge leaky_relu score

// ---------------------------------------------------------------------------
// Init: zero accumulator, -inf segment max, zero denom
// ---------------------------------------------------------------------------
__global__ void k_init(int N) {
    int i = blockIdx.x * blockDim.x + threadIdx.x;
    if (i < N * DIM) g_acc[i] = 0.0f;
    if (i < N) { g_emax[i] = -INFINITY; g_denom[i] = 0.0f; }
}

// ---------------------------------------------------------------------------
// GEMM: h = x @ W.  Block = 256 threads, 64 rows per block.
// W (16 KB) + transposed x tile (17.4 KB) in smem. Each thread: 4 rows x 4 cols.
// ---------------------------------------------------------------------------
__global__ void k_gemm(const float* __restrict__ x, const float* __restrict__ W,
                       int N) {
    __shared__ float sW[64 * 64];
    __shared__ float sX[64][68];   // [k][row], padded stride 68

    int tid = threadIdx.x;
    int row0 = blockIdx.x * 64;

    for (int i = tid; i < 64 * 64; i += 256) sW[i] = W[i];
    for (int i = tid; i < 64 * 64; i += 256) {
        int r = i >> 6, c = i & 63;
        int gr = row0 + r;
        sX[c][r] = (gr < N) ? x[gr * 64 + c] : 0.0f;
    }
    __syncthreads();

    int tc = tid & 15;   // column group: cols tc*4..tc*4+3
    int tr = tid >> 4;   // row group:    rows tr*4..tr*4+3

    float acc[4][4] = {};
#pragma unroll
    for (int k = 0; k < 64; k++) {
        float4 wv = *(const float4*)&sW[k * 64 + tc * 4];
        float4 xv = *(const float4*)&sX[k][tr * 4];
        float xa[4] = {xv.x, xv.y, xv.z, xv.w};
        float wa[4] = {wv.x, wv.y, wv.z, wv.w};
#pragma unroll
        for (int i = 0; i < 4; i++)
#pragma unroll
            for (int j = 0; j < 4; j++)
                acc[i][j] += xa[i] * wa[j];
    }

#pragma unroll
    for (int i = 0; i < 4; i++) {
        int gr = row0 + tr * 4 + i;
        if (gr < N) {
            float4 o = {acc[i][0], acc[i][1], acc[i][2], acc[i][3]};
            *(float4*)&g_h[gr * 64 + tc * 4] = o;
        }
    }
}

// ---------------------------------------------------------------------------
// Per-node attention terms: a_s = h . att_src, a_d = h . att_dst (warp/row)
// ---------------------------------------------------------------------------
__global__ void k_attn(const float* __restrict__ att_src,
                       const float* __restrict__ att_dst, int N) {
    int row  = (blockIdx.x * blockDim.x + threadIdx.x) >> 5;
    int lane = threadIdx.x & 31;
    if (row >= N) return;
    float h0 = g_h[row * 64 + lane];
    float h1 = g_h[row * 64 + 32 + lane];
    float as = h0 * att_src[lane] + h1 * att_src[lane + 32];
    float ad = h0 * att_dst[lane] + h1 * att_dst[lane + 32];
#pragma unroll
    for (int o = 16; o; o >>= 1) {
        as += __shfl_xor_sync(0xffffffffu, as, o);
        ad += __shfl_xor_sync(0xffffffffu, ad, o);
    }
    if (lane == 0) { g_as[row] = as; g_ad[row] = ad; }
}

// ---------------------------------------------------------------------------
// Edge pass A: e = leaky_relu(a_s[src] + a_d[dst]); segment atomicMax.
// Virtual edges [E, E+N) are self-loops.  edge_index is int32.
// ---------------------------------------------------------------------------
__global__ void k_edge_a(const int* __restrict__ ei, int N, int E) {
    int i = blockIdx.x * blockDim.x + threadIdx.x;
    int T = E + N;
    if (i >= T) return;
    int s, d;
    if (i < E) { s = ei[i]; d = ei[E + i]; }
    else       { s = d = i - E; }
    float e = g_as[s] + g_ad[d];
    e = (e > 0.0f) ? e : 0.2f * e;
    g_e[i] = e;
    float* addr = &g_emax[d];
    if (e >= 0.0f) atomicMax((int*)addr, __float_as_int(e));
    else           atomicMin((unsigned int*)addr, __float_as_uint(e));
}

// ---------------------------------------------------------------------------
// Edge pass B (fused): ex = exp(e - max[d]); denom[d] += ex;
// acc[d] += ex * h[s]  via red.global.add.v4.f32 (16 threads / edge).
// ---------------------------------------------------------------------------
__global__ void k_edge_b(const int* __restrict__ ei, int N, int E) {
    int T = E + N;
    int gidx = blockIdx.x * 16 + (threadIdx.x >> 4);
    int sub  = threadIdx.x & 15;
    bool valid = gidx < T;

    int s = 0, d = 0;
    float w = 0.0f;
    if (valid && sub == 0) {
        if (gidx < E) { s = ei[gidx]; d = ei[E + gidx]; }
        else          { s = d = gidx - E; }
        float ex = __expf(g_e[gidx] - g_emax[d]);
        atomicAdd(&g_denom[d], ex);
        w = ex;
    }
    s = __shfl_sync(0xffffffffu, s, 0, 16);
    d = __shfl_sync(0xffffffffu, d, 0, 16);
    w = __shfl_sync(0xffffffffu, w, 0, 16);
    if (!valid) return;

    float4 hv = *(const float4*)&g_h[s * 64 + sub * 4];
    float vx = hv.x * w, vy = hv.y * w, vz = hv.z * w, vw = hv.w * w;
    float* dst = &g_acc[d * 64 + sub * 4];
    asm volatile("red.global.add.v4.f32 [%0], {%1,%2,%3,%4};"
                 :: "l"(dst), "f"(vx), "f"(vy), "f"(vz), "f"(vw) : "memory");
}

// ---------------------------------------------------------------------------
// Epilogue: out = acc/denom + bias, then LayerNorm(out_dim). Warp per row.
// ---------------------------------------------------------------------------
__global__ void k_final(const float* __restrict__ bias,
                        const float* __restrict__ gamma,
                        const float* __restrict__ beta,
                        float* __restrict__ out, int N) {
    int row  = (blockIdx.x * blockDim.x + threadIdx.x) >> 5;
    int lane = threadIdx.x & 31;
    if (row >= N) return;
    float inv = 1.0f / g_denom[row];
    float v0 = g_acc[row * 64 + lane]      * inv + bias[lane];
    float v1 = g_acc[row * 64 + 32 + lane] * inv + bias[lane + 32];
    float sum = v0 + v1;
#pragma unroll
    for (int o = 16; o; o >>= 1) sum += __shfl_xor_sync(0xffffffffu, sum, o);
    float mu = sum * (1.0f / 64.0f);
    float d0 = v0 - mu, d1 = v1 - mu;
    float sq = d0 * d0 + d1 * d1;
#pragma unroll
    for (int o = 16; o; o >>= 1) sq += __shfl_xor_sync(0xffffffffu, sq, o);
    float rs = rsqrtf(sq * (1.0f / 64.0f) + 1e-5f);
    out[row * 64 + lane]      = d0 * rs * gamma[lane]      + beta[lane];
    out[row * 64 + 32 + lane] = d1 * rs * gamma[lane + 32] + beta[lane + 32];
}

// ---------------------------------------------------------------------------
extern "C" void kernel_launch(void* const* d_in, const int* in_sizes, int n_in,
                              void* d_out, int out_size) {
    const float* x       = (const float*)d_in[0];
    const int*   ei      = (const int*)d_in[1];     // int32 (JAX x64 disabled)
    const float* W       = (const float*)d_in[2];
    const float* att_src = (const float*)d_in[3];
    const float* att_dst = (const float*)d_in[4];
    const float* bias    = (const float*)d_in[5];
    const float* gamma   = (const float*)d_in[6];
    const float* beta    = (const float*)d_in[7];
    float*       out     = (float*)d_out;

    int N = in_sizes[0] / DIM;
    int E = in_sizes[1] / 2;
    int T = E + N;

    k_init  <<<(N * DIM + 255) / 256, 256>>>(N);
    k_gemm  <<<(N + 63) / 64,        256>>>(x, W, N);
    k_attn  <<<(N + 7) / 8,          256>>>(att_src, att_dst, N);
    k_edge_a<<<(T + 255) / 256,      256>>>(ei, N, E);
    k_edge_b<<<(T + 15) / 16,        256>>>(ei, N, E);
    k_final <<<(N + 7) / 8,          256>>>(bias, gamma, beta, out, N);
}

// round 3
// speedup vs baseline: 1.0832x; 1.0832x over previous
#include <cuda_runtime.h>
#include <math.h>

#define DIM 64
#define N_MAX 100000
#define E_MAX 1200000

__device__ float g_h[N_MAX * DIM];      // h = x @ W
__device__ float g_acc[N_MAX * DIM];    // unnormalized weighted sums
__device__ float g_as[N_MAX];
__device__ float g_ad[N_MAX];
__device__ float g_denom[N_MAX];

// ---------------------------------------------------------------------------
// Init: zero accumulator + denom
// ---------------------------------------------------------------------------
__global__ void k_init(int N) {
    int i = blockIdx.x * blockDim.x + threadIdx.x;
    if (i < N * 16) ((float4*)g_acc)[i] = make_float4(0.f, 0.f, 0.f, 0.f);
    if (i < N) g_denom[i] = 0.0f;
}

// ---------------------------------------------------------------------------
// GEMM: h = x @ W, fused per-node attention dots a_s = h.att_src, a_d = h.att_dst.
// Block = 256 threads, 64 rows per block. Each thread: 4 rows x 4 cols.
// ---------------------------------------------------------------------------
__global__ void k_gemm(const float* __restrict__ x, const float* __restrict__ W,
                       const float* __restrict__ att_src,
                       const float* __restrict__ att_dst, int N) {
    __shared__ float sW[64 * 64];
    __shared__ float sX[64][68];   // [k][row], padded

    int tid = threadIdx.x;
    int row0 = blockIdx.x * 64;

    for (int i = tid; i < 64 * 64; i += 256) sW[i] = W[i];
    for (int i = tid; i < 64 * 64; i += 256) {
        int r = i >> 6, c = i & 63;
        int gr = row0 + r;
        sX[c][r] = (gr < N) ? x[gr * 64 + c] : 0.0f;
    }
    __syncthreads();

    int tc = tid & 15;   // cols tc*4..tc*4+3
    int tr = tid >> 4;   // rows tr*4..tr*4+3

    float acc[4][4] = {};
#pragma unroll
    for (int k = 0; k < 64; k++) {
        float4 wv = *(const float4*)&sW[k * 64 + tc * 4];
        float4 xv = *(const float4*)&sX[k][tr * 4];
        float xa[4] = {xv.x, xv.y, xv.z, xv.w};
        float wa[4] = {wv.x, wv.y, wv.z, wv.w};
#pragma unroll
        for (int i = 0; i < 4; i++)
#pragma unroll
            for (int j = 0; j < 4; j++)
                acc[i][j] += xa[i] * wa[j];
    }

    // attention vectors for this thread's 4 columns
    float4 asv = *(const float4*)&att_src[tc * 4];
    float4 adv = *(const float4*)&att_dst[tc * 4];
    float sa[4] = {asv.x, asv.y, asv.z, asv.w};
    float da[4] = {adv.x, adv.y, adv.z, adv.w};

#pragma unroll
    for (int i = 0; i < 4; i++) {
        int gr = row0 + tr * 4 + i;
        float ps = acc[i][0]*sa[0] + acc[i][1]*sa[1] + acc[i][2]*sa[2] + acc[i][3]*sa[3];
        float pd = acc[i][0]*da[0] + acc[i][1]*da[1] + acc[i][2]*da[2] + acc[i][3]*da[3];
        // reduce across the 16 tc lanes (contiguous within warp halves)
#pragma unroll
        for (int o = 8; o; o >>= 1) {
            ps += __shfl_down_sync(0xffffffffu, ps, o, 16);
            pd += __shfl_down_sync(0xffffffffu, pd, o, 16);
        }
        if (gr < N) {
            float4 o = {acc[i][0], acc[i][1], acc[i][2], acc[i][3]};
            *(float4*)&g_h[gr * 64 + tc * 4] = o;
            if (tc == 0) { g_as[gr] = ps; g_ad[gr] = pd; }
        }
    }
}

// ---------------------------------------------------------------------------
// Fused edge pass (no max-subtraction — scores bounded, exp() safe):
// w = exp(leaky_relu(a_s[s] + a_d[d])); denom[d] += w;
// acc[d] += w * h[s]  via red.global.add.v4.f32 (16 threads / edge).
// Virtual edges [E, E+N) are self-loops.
// ---------------------------------------------------------------------------
__global__ void k_edge(const int* __restrict__ ei, int N, int E) {
    int T = E + N;
    int gidx = blockIdx.x * 16 + (threadIdx.x >> 4);
    int sub  = threadIdx.x & 15;
    bool valid = gidx < T;

    int s = 0, d = 0;
    float w = 0.0f;
    if (valid && sub == 0) {
        if (gidx < E) { s = __ldg(&ei[gidx]); d = __ldg(&ei[E + gidx]); }
        else          { s = d = gidx - E; }
        float e = g_as[s] + g_ad[d];
        e = (e > 0.0f) ? e : 0.2f * e;
        float ex = __expf(e);
        atomicAdd(&g_denom[d], ex);
        w = ex;
    }
    s = __shfl_sync(0xffffffffu, s, 0, 16);
    d = __shfl_sync(0xffffffffu, d, 0, 16);
    w = __shfl_sync(0xffffffffu, w, 0, 16);
    if (!valid) return;

    float4 hv = *(const float4*)&g_h[s * 64 + sub * 4];
    float vx = hv.x * w, vy = hv.y * w, vz = hv.z * w, vw = hv.w * w;
    float* dst = &g_acc[d * 64 + sub * 4];
    asm volatile("red.global.add.v4.f32 [%0], {%1,%2,%3,%4};"
                 :: "l"(dst), "f"(vx), "f"(vy), "f"(vz), "f"(vw) : "memory");
}

// ---------------------------------------------------------------------------
// Epilogue: out = acc/denom + bias, then LayerNorm. Warp per row.
// ---------------------------------------------------------------------------
__global__ void k_final(const float* __restrict__ bias,
                        const float* __restrict__ gamma,
                        const float* __restrict__ beta,
                        float* __restrict__ out, int N) {
    int row  = (blockIdx.x * blockDim.x + threadIdx.x) >> 5;
    int lane = threadIdx.x & 31;
    if (row >= N) return;
    float inv = 1.0f / g_denom[row];
    float v0 = g_acc[row * 64 + lane]      * inv + bias[lane];
    float v1 = g_acc[row * 64 + 32 + lane] * inv + bias[lane + 32];
    float sum = v0 + v1;
#pragma unroll
    for (int o = 16; o; o >>= 1) sum += __shfl_xor_sync(0xffffffffu, sum, o);
    float mu = sum * (1.0f / 64.0f);
    float d0 = v0 - mu, d1 = v1 - mu;
    float sq = d0 * d0 + d1 * d1;
#pragma unroll
    for (int o = 16; o; o >>= 1) sq += __shfl_xor_sync(0xffffffffu, sq, o);
    float rs = rsqrtf(sq * (1.0f / 64.0f) + 1e-5f);
    out[row * 64 + lane]      = d0 * rs * gamma[lane]      + beta[lane];
    out[row * 64 + 32 + lane] = d1 * rs * gamma[lane + 32] + beta[lane + 32];
}

// ---------------------------------------------------------------------------
extern "C" void kernel_launch(void* const* d_in, const int* in_sizes, int n_in,
                              void* d_out, int out_size) {
    const float* x       = (const float*)d_in[0];
    const int*   ei      = (const int*)d_in[1];     // int32 (JAX x64 disabled)
    const float* W       = (const float*)d_in[2];
    const float* att_src = (const float*)d_in[3];
    const float* att_dst = (const float*)d_in[4];
    const float* bias    = (const float*)d_in[5];
    const float* gamma   = (const float*)d_in[6];
    const float* beta    = (const float*)d_in[7];
    float*       out     = (float*)d_out;

    int N = in_sizes[0] / DIM;
    int E = in_sizes[1] / 2;
    int T = E + N;

    k_init <<<(N * 16 + 255) / 256, 256>>>(N);
    k_gemm <<<(N + 63) / 64,       256>>>(x, W, att_src, att_dst, N);
    k_edge <<<(T + 15) / 16,       256>>>(ei, N, E);
    k_final<<<(N + 7) / 8,         256>>>(bias, gamma, beta, out, N);
}

// round 5
// speedup vs baseline: 1.3507x; 1.2469x over previous
#include <cuda_runtime.h>
#include <math.h>

#define DIM 64
#define N_MAX 100000
#define E_MAX 1200000
#define T_MAX (E_MAX + N_MAX)
#define NSCAN_MAX 128

__device__ float g_h[N_MAX * DIM];   // h = x @ W
__device__ float g_as[N_MAX];
__device__ float g_ad[N_MAX];
__device__ int   g_cnt[N_MAX];       // per-dst degree
__device__ int   g_excl[N_MAX];      // block-local exclusive scan
__device__ int   g_bsum[NSCAN_MAX];  // per-scanblock totals
__device__ int   g_boff[NSCAN_MAX];  // scanned block offsets
__device__ int   g_off[N_MAX];       // segment start
__device__ int   g_cur[N_MAX];       // scatter cursor
__device__ int   g_sE[T_MAX];        // dst-sorted src
__device__ float g_wE[T_MAX];        // dst-sorted weight exp(leaky(score))

// ---------------------------------------------------------------------------
__global__ void k_zero(int N) {
    int i = blockIdx.x * blockDim.x + threadIdx.x;
    if (i < N) g_cnt[i] = 0;
}

// ---------------------------------------------------------------------------
// GEMM: h = x @ W, fused a_s = h.att_src, a_d = h.att_dst
// ---------------------------------------------------------------------------
__global__ void k_gemm(const float* __restrict__ x, const float* __restrict__ W,
                       const float* __restrict__ att_src,
                       const float* __restrict__ att_dst, int N) {
    __shared__ float sW[64 * 64];
    __shared__ float sX[64][68];

    int tid = threadIdx.x;
    int row0 = blockIdx.x * 64;

    for (int i = tid; i < 64 * 64; i += 256) sW[i] = W[i];
    for (int i = tid; i < 64 * 64; i += 256) {
        int r = i >> 6, c = i & 63;
        int gr = row0 + r;
        sX[c][r] = (gr < N) ? x[gr * 64 + c] : 0.0f;
    }
    __syncthreads();

    int tc = tid & 15;
    int tr = tid >> 4;

    float acc[4][4] = {};
#pragma unroll
    for (int k = 0; k < 64; k++) {
        float4 wv = *(const float4*)&sW[k * 64 + tc * 4];
        float4 xv = *(const float4*)&sX[k][tr * 4];
        float xa[4] = {xv.x, xv.y, xv.z, xv.w};
        float wa[4] = {wv.x, wv.y, wv.z, wv.w};
#pragma unroll
        for (int i = 0; i < 4; i++)
#pragma unroll
            for (int j = 0; j < 4; j++)
                acc[i][j] += xa[i] * wa[j];
    }

    float4 asv = *(const float4*)&att_src[tc * 4];
    float4 adv = *(const float4*)&att_dst[tc * 4];
    float sa[4] = {asv.x, asv.y, asv.z, asv.w};
    float da[4] = {adv.x, adv.y, adv.z, adv.w};

#pragma unroll
    for (int i = 0; i < 4; i++) {
        int gr = row0 + tr * 4 + i;
        float ps = acc[i][0]*sa[0] + acc[i][1]*sa[1] + acc[i][2]*sa[2] + acc[i][3]*sa[3];
        float pd = acc[i][0]*da[0] + acc[i][1]*da[1] + acc[i][2]*da[2] + acc[i][3]*da[3];
#pragma unroll
        for (int o = 8; o; o >>= 1) {
            ps += __shfl_down_sync(0xffffffffu, ps, o, 16);
            pd += __shfl_down_sync(0xffffffffu, pd, o, 16);
        }
        if (gr < N) {
            float4 o = {acc[i][0], acc[i][1], acc[i][2], acc[i][3]};
            *(float4*)&g_h[gr * 64 + tc * 4] = o;
            if (tc == 0) { g_as[gr] = ps; g_ad[gr] = pd; }
        }
    }
}

// ---------------------------------------------------------------------------
// Histogram of dst (self-loops are virtual edges [E, E+N))
// ---------------------------------------------------------------------------
__global__ void k_hist(const int* __restrict__ ei, int N, int E) {
    int i = blockIdx.x * blockDim.x + threadIdx.x;
    if (i >= E + N) return;
    int d = (i < E) ? ei[E + i] : (i - E);
    atomicAdd(&g_cnt[d], 1);
}

// ---------------------------------------------------------------------------
// Scan stage 1: block-level exclusive scan of g_cnt -> g_excl, totals -> g_bsum
// ---------------------------------------------------------------------------
__device__ __forceinline__ int block_scan_1024(int v, int t, int* total) {
    int lane = t & 31, wid = t >> 5;
    int x = v;
#pragma unroll
    for (int o = 1; o < 32; o <<= 1) {
        int y = __shfl_up_sync(0xffffffffu, x, o);
        if (lane >= o) x += y;
    }
    __shared__ int ws[32];
    if (lane == 31) ws[wid] = x;
    __syncthreads();
    if (wid == 0) {
        int s = ws[lane];
#pragma unroll
        for (int o = 1; o < 32; o <<= 1) {
            int y = __shfl_up_sync(0xffffffffu, s, o);
            if (lane >= o) s += y;
        }
        ws[lane] = s;
    }
    __syncthreads();
    int add = wid ? ws[wid - 1] : 0;
    *total = ws[31];
    return x + add - v;   // exclusive
}

__global__ void k_scan1(int n) {
    int t = threadIdx.x;
    int i = blockIdx.x * 1024 + t;
    int v = (i < n) ? g_cnt[i] : 0;
    int total;
    int ex = block_scan_1024(v, t, &total);
    if (i < n) g_excl[i] = ex;
    if (t == 0) g_bsum[blockIdx.x] = total;
}

// Scan stage 2: single block scans g_bsum -> g_boff
__global__ void k_scan2(int nb) {
    int t = threadIdx.x;
    int v = (t < nb) ? g_bsum[t] : 0;
    int total;
    int ex = block_scan_1024(v, t, &total);
    if (t < nb) g_boff[t] = ex;
}

// Scan stage 3: add block offsets, init cursor
__global__ void k_scan_add(int n) {
    int i = blockIdx.x * 1024 + threadIdx.x;
    if (i >= n) return;
    int v = g_excl[i] + g_boff[blockIdx.x];
    g_off[i] = v;
    g_cur[i] = v;
}

// ---------------------------------------------------------------------------
// Scatter: per edge compute w = exp(leaky_relu(a_s[s]+a_d[d])), place into
// dst-sorted position.
// ---------------------------------------------------------------------------
__global__ void k_scatter(const int* __restrict__ ei, int N, int E) {
    int i = blockIdx.x * blockDim.x + threadIdx.x;
    if (i >= E + N) return;
    int s, d;
    if (i < E) { s = ei[i]; d = ei[E + i]; }
    else       { s = d = i - E; }
    float e = g_as[s] + g_ad[d];
    e = (e > 0.0f) ? e : 0.2f * e;
    float w = __expf(e);
    int pos = atomicAdd(&g_cur[d], 1);
    g_sE[pos] = s;
    g_wE[pos] = w;
}

// ---------------------------------------------------------------------------
// Gather + normalize + bias + LayerNorm, fused. Half-warp (16 lanes) per node.
// ---------------------------------------------------------------------------
__global__ void k_gather(const float* __restrict__ bias,
                         const float* __restrict__ gamma,
                         const float* __restrict__ beta,
                         float* __restrict__ out, int N) {
    int idx  = blockIdx.x * blockDim.x + threadIdx.x;
    int node = idx >> 4;
    int sub  = idx & 15;
    unsigned hm = 0xFFFFu << (threadIdx.x & 16);   // half-warp mask
    if (node >= N) return;

    int start = g_off[node];
    int deg   = g_cnt[node];

    float4 acc = make_float4(0.f, 0.f, 0.f, 0.f);
    float wsum = 0.0f;

    for (int base = 0; base < deg; base += 16) {
        int e  = start + base + sub;
        int sj = 0; float wj = 0.0f;
        if (base + sub < deg) { sj = g_sE[e]; wj = g_wE[e]; }
        int m = min(16, deg - base);
        for (int j = 0; j < m; j++) {
            int   s = __shfl_sync(hm, sj, j, 16);
            float w = __shfl_sync(hm, wj, j, 16);
            float4 hv = *(const float4*)&g_h[s * 64 + sub * 4];
            acc.x = fmaf(w, hv.x, acc.x);
            acc.y = fmaf(w, hv.y, acc.y);
            acc.z = fmaf(w, hv.z, acc.z);
            acc.w = fmaf(w, hv.w, acc.w);
            wsum += w;
        }
    }

    float inv = 1.0f / wsum;
    float4 bv = *(const float4*)&bias[sub * 4];
    float v0 = acc.x * inv + bv.x;
    float v1 = acc.y * inv + bv.y;
    float v2 = acc.z * inv + bv.z;
    float v3 = acc.w * inv + bv.w;

    float sum = v0 + v1 + v2 + v3;
#pragma unroll
    for (int o = 8; o; o >>= 1) sum += __shfl_xor_sync(hm, sum, o, 16);
    float mu = sum * (1.0f / 64.0f);

    float d0 = v0 - mu, d1 = v1 - mu, d2 = v2 - mu, d3 = v3 - mu;
    float sq = d0*d0 + d1*d1 + d2*d2 + d3*d3;
#pragma unroll
    for (int o = 8; o; o >>= 1) sq += __shfl_xor_sync(hm, sq, o, 16);
    float rs = rsqrtf(sq * (1.0f / 64.0f) + 1e-5f);

    float4 gv = *(const float4*)&gamma[sub * 4];
    float4 be = *(const float4*)&beta[sub * 4];
    float4 o4;
    o4.x = d0 * rs * gv.x + be.x;
    o4.y = d1 * rs * gv.y + be.y;
    o4.z = d2 * rs * gv.z + be.z;
    o4.w = d3 * rs * gv.w + be.w;
    *(float4*)&out[node * 64 + sub * 4] = o4;
}

// ---------------------------------------------------------------------------
extern "C" void kernel_launch(void* const* d_in, const int* in_sizes, int n_in,
                              void* d_out, int out_size) {
    const float* x       = (const float*)d_in[0];
    const int*   ei      = (const int*)d_in[1];     // int32
    const float* W       = (const float*)d_in[2];
    const float* att_src = (const float*)d_in[3];
    const float* att_dst = (const float*)d_in[4];
    const float* bias    = (const float*)d_in[5];
    const float* gamma   = (const float*)d_in[6];
    const float* beta    = (const float*)d_in[7];
    float*       out     = (float*)d_out;

    int N = in_sizes[0] / DIM;
    int E = in_sizes[1] / 2;
    int T = E + N;
    int nScanBlocks = (N + 1023) / 1024;   // <= NSCAN_MAX

    k_zero    <<<(N + 255) / 256, 256>>>(N);
    k_gemm    <<<(N + 63) / 64,   256>>>(x, W, att_src, att_dst, N);
    k_hist    <<<(T + 255) / 256, 256>>>(ei, N, E);
    k_scan1   <<<nScanBlocks, 1024>>>(N);
    k_scan2   <<<1, 1024>>>(nScanBlocks);
    k_scan_add<<<nScanBlocks, 1024>>>(N);
    k_scatter <<<(T + 255) / 256, 256>>>(ei, N, E);
    k_gather  <<<(N * 16 + 255) / 256, 256>>>(bias, gamma, beta, out, N);
}

// round 7
// speedup vs baseline: 1.6057x; 1.1888x over previous
#include <cuda_runtime.h>
#include <cuda_fp16.h>
#include <math.h>

#define DIM 64
#define N_MAX 100000
#define E_MAX 1200000
#define T_MAX (E_MAX + N_MAX)
#define NSCAN_MAX 128

__device__ __half2 g_h16[N_MAX * 32];  // h = x @ W, fp16 (gather-only consumer)
__device__ float g_as[N_MAX];
__device__ float g_ad[N_MAX];
__device__ int   g_cnt[N_MAX];       // per-dst degree
__device__ int   g_excl[N_MAX];      // block-local exclusive scan
__device__ int   g_bsum[NSCAN_MAX];
__device__ int   g_boff[NSCAN_MAX];
__device__ int   g_off[N_MAX];       // segment start
__device__ int   g_cur[N_MAX];       // scatter cursor
__device__ int2  g_swE[T_MAX];       // dst-sorted (src, weight-bits)

// ---------------------------------------------------------------------------
__global__ void k_zero(int N) {
    int i = blockIdx.x * blockDim.x + threadIdx.x;
    if (i < N) g_cnt[i] = 0;
}

// ---------------------------------------------------------------------------
// GEMM: h = x @ W (stored fp16), fused a_s = h.att_src, a_d = h.att_dst (fp32)
// ---------------------------------------------------------------------------
__global__ void k_gemm(const float* __restrict__ x, const float* __restrict__ W,
                       const float* __restrict__ att_src,
                       const float* __restrict__ att_dst, int N) {
    __shared__ float sW[64 * 64];
    __shared__ float sX[64][68];

    int tid = threadIdx.x;
    int row0 = blockIdx.x * 64;

    for (int i = tid; i < 64 * 64; i += 256) sW[i] = W[i];
    for (int i = tid; i < 64 * 64; i += 256) {
        int r = i >> 6, c = i & 63;
        int gr = row0 + r;
        sX[c][r] = (gr < N) ? x[gr * 64 + c] : 0.0f;
    }
    __syncthreads();

    int tc = tid & 15;
    int tr = tid >> 4;

    float acc[4][4] = {};
#pragma unroll
    for (int k = 0; k < 64; k++) {
        float4 wv = *(const float4*)&sW[k * 64 + tc * 4];
        float4 xv = *(const float4*)&sX[k][tr * 4];
        float xa[4] = {xv.x, xv.y, xv.z, xv.w};
        float wa[4] = {wv.x, wv.y, wv.z, wv.w};
#pragma unroll
        for (int i = 0; i < 4; i++)
#pragma unroll
            for (int j = 0; j < 4; j++)
                acc[i][j] += xa[i] * wa[j];
    }

    float4 asv = *(const float4*)&att_src[tc * 4];
    float4 adv = *(const float4*)&att_dst[tc * 4];
    float sa[4] = {asv.x, asv.y, asv.z, asv.w};
    float da[4] = {adv.x, adv.y, adv.z, adv.w};

#pragma unroll
    for (int i = 0; i < 4; i++) {
        int gr = row0 + tr * 4 + i;
        float ps = acc[i][0]*sa[0] + acc[i][1]*sa[1] + acc[i][2]*sa[2] + acc[i][3]*sa[3];
        float pd = acc[i][0]*da[0] + acc[i][1]*da[1] + acc[i][2]*da[2] + acc[i][3]*da[3];
#pragma unroll
        for (int o = 8; o; o >>= 1) {
            ps += __shfl_down_sync(0xffffffffu, ps, o, 16);
            pd += __shfl_down_sync(0xffffffffu, pd, o, 16);
        }
        if (gr < N) {
            __half2 h0 = __floats2half2_rn(acc[i][0], acc[i][1]);
            __half2 h1 = __floats2half2_rn(acc[i][2], acc[i][3]);
            g_h16[gr * 32 + tc * 2]     = h0;
            g_h16[gr * 32 + tc * 2 + 1] = h1;
            if (tc == 0) { g_as[gr] = ps; g_ad[gr] = pd; }
        }
    }
}

// ---------------------------------------------------------------------------
// Histogram of dst (self-loops are virtual edges [E, E+N))
// ---------------------------------------------------------------------------
__global__ void k_hist(const int* __restrict__ ei, int N, int E) {
    int i = blockIdx.x * blockDim.x + threadIdx.x;
    if (i >= E + N) return;
    int d = (i < E) ? ei[E + i] : (i - E);
    atomicAdd(&g_cnt[d], 1);
}

// ---------------------------------------------------------------------------
// Scan stages
// ---------------------------------------------------------------------------
__device__ __forceinline__ int block_scan_1024(int v, int t, int* total) {
    int lane = t & 31, wid = t >> 5;
    int x = v;
#pragma unroll
    for (int o = 1; o < 32; o <<= 1) {
        int y = __shfl_up_sync(0xffffffffu, x, o);
        if (lane >= o) x += y;
    }
    __shared__ int ws[32];
    if (lane == 31) ws[wid] = x;
    __syncthreads();
    if (wid == 0) {
        int s = ws[lane];
#pragma unroll
        for (int o = 1; o < 32; o <<= 1) {
            int y = __shfl_up_sync(0xffffffffu, s, o);
            if (lane >= o) s += y;
        }
        ws[lane] = s;
    }
    __syncthreads();
    int add = wid ? ws[wid - 1] : 0;
    *total = ws[31];
    return x + add - v;
}

__global__ void k_scan1(int n) {
    int t = threadIdx.x;
    int i = blockIdx.x * 1024 + t;
    int v = (i < n) ? g_cnt[i] : 0;
    int total;
    int ex = block_scan_1024(v, t, &total);
    if (i < n) g_excl[i] = ex;
    if (t == 0) g_bsum[blockIdx.x] = total;
}

__global__ void k_scan2(int nb) {
    int t = threadIdx.x;
    int v = (t < nb) ? g_bsum[t] : 0;
    int total;
    int ex = block_scan_1024(v, t, &total);
    if (t < nb) g_boff[t] = ex;
}

__global__ void k_scan_add(int n) {
    int i = blockIdx.x * 1024 + threadIdx.x;
    if (i >= n) return;
    int v = g_excl[i] + g_boff[blockIdx.x];
    g_off[i] = v;
    g_cur[i] = v;
}

// ---------------------------------------------------------------------------
// Scatter: per edge compute w = exp(leaky_relu(a_s[s]+a_d[d])),
// place packed (s, w) into dst-sorted position.
// ---------------------------------------------------------------------------
__global__ void k_scatter(const int* __restrict__ ei, int N, int E) {
    int i = blockIdx.x * blockDim.x + threadIdx.x;
    if (i >= E + N) return;
    int s, d;
    if (i < E) { s = ei[i]; d = ei[E + i]; }
    else       { s = d = i - E; }
    float e = g_as[s] + g_ad[d];
    e = (e > 0.0f) ? e : 0.2f * e;
    float w = __expf(e);
    int pos = atomicAdd(&g_cur[d], 1);
    g_swE[pos] = make_int2(s, __float_as_int(w));
}

// ---------------------------------------------------------------------------
// Gather (fp16 h) + normalize + bias + LayerNorm, fused. Half-warp per node.
// ---------------------------------------------------------------------------
__global__ void k_gather(const float* __restrict__ bias,
                         const float* __restrict__ gamma,
                         const float* __restrict__ beta,
                         float* __restrict__ out, int N) {
    int idx  = blockIdx.x * blockDim.x + threadIdx.x;
    int node = idx >> 4;
    int sub  = idx & 15;
    unsigned hm = 0xFFFFu << (threadIdx.x & 16);   // half-warp mask
    if (node >= N) return;

    int start = g_off[node];
    int deg   = g_cnt[node];

    float4 acc = make_float4(0.f, 0.f, 0.f, 0.f);
    float wsum = 0.0f;

    for (int base = 0; base < deg; base += 16) {
        int sj = 0; float wj = 0.0f;
        if (base + sub < deg) {
            int2 sw = g_swE[start + base + sub];
            sj = sw.x; wj = __int_as_float(sw.y);
        }
        int m = min(16, deg - base);
        for (int j = 0; j < m; j++) {
            int   s = __shfl_sync(hm, sj, j, 16);
            float w = __shfl_sync(hm, wj, j, 16);
            uint2 raw = *(const uint2*)&g_h16[s * 32 + sub * 2];
            float2 f0 = __half22float2(*(__half2*)&raw.x);
            float2 f1 = __half22float2(*(__half2*)&raw.y);
            acc.x = fmaf(w, f0.x, acc.x);
            acc.y = fmaf(w, f0.y, acc.y);
            acc.z = fmaf(w, f1.x, acc.z);
            acc.w = fmaf(w, f1.y, acc.w);
            wsum += w;
        }
    }

    float inv = 1.0f / wsum;
    float4 bv = *(const float4*)&bias[sub * 4];
    float v0 = acc.x * inv + bv.x;
    float v1 = acc.y * inv + bv.y;
    float v2 = acc.z * inv + bv.z;
    float v3 = acc.w * inv + bv.w;

    float sum = v0 + v1 + v2 + v3;
#pragma unroll
    for (int o = 8; o; o >>= 1) sum += __shfl_xor_sync(hm, sum, o, 16);
    float mu = sum * (1.0f / 64.0f);

    float d0 = v0 - mu, d1 = v1 - mu, d2 = v2 - mu, d3 = v3 - mu;
    float sq = d0*d0 + d1*d1 + d2*d2 + d3*d3;
#pragma unroll
    for (int o = 8; o; o >>= 1) sq += __shfl_xor_sync(hm, sq, o, 16);
    float rs = rsqrtf(sq * (1.0f / 64.0f) + 1e-5f);

    float4 gv = *(const float4*)&gamma[sub * 4];
    float4 be = *(const float4*)&beta[sub * 4];
    float4 o4;
    o4.x = d0 * rs * gv.x + be.x;
    o4.y = d1 * rs * gv.y + be.y;
    o4.z = d2 * rs * gv.z + be.z;
    o4.w = d3 * rs * gv.w + be.w;
    *(float4*)&out[node * 64 + sub * 4] = o4;
}

// ---------------------------------------------------------------------------
extern "C" void kernel_launch(void* const* d_in, const int* in_sizes, int n_in,
                              void* d_out, int out_size) {
    const float* x       = (const float*)d_in[0];
    const int*   ei      = (const int*)d_in[1];     // int32
    const float* W       = (const float*)d_in[2];
    const float* att_src = (const float*)d_in[3];
    const float* att_dst = (const float*)d_in[4];
    const float* bias    = (const float*)d_in[5];
    const float* gamma   = (const float*)d_in[6];
    const float* beta    = (const float*)d_in[7];
    float*       out     = (float*)d_out;

    int N = in_sizes[0] / DIM;
    int E = in_sizes[1] / 2;
    int T = E + N;
    int nScanBlocks = (N + 1023) / 1024;   // <= NSCAN_MAX

    k_zero    <<<(N + 255) / 256, 256>>>(N);
    k_gemm    <<<(N + 63) / 64,   256>>>(x, W, att_src, att_dst, N);
    k_hist    <<<(T + 255) / 256, 256>>>(ei, N, E);
    k_scan1   <<<nScanBlocks, 1024>>>(N);
    k_scan2   <<<1, 1024>>>(nScanBlocks);
    k_scan_add<<<nScanBlocks, 1024>>>(N);
    k_scatter <<<(T + 255) / 256, 256>>>(ei, N, E);
    k_gather  <<<(N * 16 + 255) / 256, 256>>>(bias, gamma, beta, out, N);
}

// round 8
// speedup vs baseline: 1.8625x; 1.1600x over previous
#include <cuda_runtime.h>
#include <cuda_fp16.h>
#include <math.h>

#define DIM 64
#define N_MAX 100000
#define E_MAX 1200000
#define T_MAX (E_MAX + N_MAX)
#define NSCAN_MAX 128

__device__ __half2 g_h16[N_MAX * 32];  // h = x @ W, fp16 (gather-only consumer)
__device__ float g_as[N_MAX];
__device__ float g_ad[N_MAX];
__device__ int   g_cnt[N_MAX];
__device__ int   g_excl[N_MAX];
__device__ int   g_bsum[NSCAN_MAX];
__device__ int   g_boff[NSCAN_MAX];
__device__ int   g_off[N_MAX];
__device__ int   g_cur[N_MAX];
__device__ int2  g_swE[T_MAX];         // dst-sorted (src, weight-bits)

// ---------------------------------------------------------------------------
__global__ void k_zero(int N) {
    int i = blockIdx.x * blockDim.x + threadIdx.x;
    if (i < N) g_cnt[i] = 0;
}

// ---------------------------------------------------------------------------
// tf32 helpers
// ---------------------------------------------------------------------------
__device__ __forceinline__ float cvt_tf32(float x) {
    unsigned o;
    asm("cvt.rna.tf32.f32 %0, %1;" : "=r"(o) : "f"(x));
    return __uint_as_float(o);
}

__device__ __forceinline__ void mma_tf32(float c[4],
                                         unsigned a0, unsigned a1, unsigned a2, unsigned a3,
                                         unsigned b0, unsigned b1) {
    asm volatile(
        "mma.sync.aligned.m16n8k8.row.col.f32.tf32.tf32.f32 "
        "{%0,%1,%2,%3},{%4,%5,%6,%7},{%8,%9},{%0,%1,%2,%3};"
        : "+f"(c[0]), "+f"(c[1]), "+f"(c[2]), "+f"(c[3])
        : "r"(a0), "r"(a1), "r"(a2), "r"(a3), "r"(b0), "r"(b1));
}

// ---------------------------------------------------------------------------
// GEMM via 3xTF32 mma (near-fp32): h = x @ W (stored fp16),
// fused a_s = h.att_src, a_d = h.att_dst (fp32), fused dst histogram tail.
// Block: 256 threads (8 warps), 128 rows. Each warp: 16 rows x 64 cols.
// ---------------------------------------------------------------------------
__global__ void k_gemm(const float* __restrict__ x, const float* __restrict__ W,
                       const float* __restrict__ att_src,
                       const float* __restrict__ att_dst,
                       const int* __restrict__ ei, int N, int E) {
    __shared__ float sWhi[64 * 72];   // stride 72: conflict-free B-frag loads
    __shared__ float sWlo[64 * 72];

    int tid  = threadIdx.x;
    int w    = tid >> 5;
    int lane = tid & 31;
    int g    = lane >> 2;     // 0..7
    int tig  = lane & 3;      // 0..3
    int row0 = blockIdx.x * 128 + w * 16 + g;   // this thread's base row
    int row8 = row0 + 8;

    // Stage W as tf32 hi/lo
    for (int i = tid; i < 64 * 64; i += 256) {
        int k = i >> 6, n = i & 63;
        float v  = W[i];
        float hi = cvt_tf32(v);
        sWhi[k * 72 + n] = hi;
        sWlo[k * 72 + n] = cvt_tf32(v - hi);
    }
    __syncthreads();

    float C[8][4] = {};

#pragma unroll
    for (int ks = 0; ks < 8; ks++) {
        int k0 = ks * 8;
        // A fragment (rows row0,row8; cols k0+tig, k0+tig+4), guarded
        float a00 = (row0 < N) ? __ldg(&x[row0 * 64 + k0 + tig])     : 0.0f;
        float a10 = (row8 < N) ? __ldg(&x[row8 * 64 + k0 + tig])     : 0.0f;
        float a01 = (row0 < N) ? __ldg(&x[row0 * 64 + k0 + tig + 4]) : 0.0f;
        float a11 = (row8 < N) ? __ldg(&x[row8 * 64 + k0 + tig + 4]) : 0.0f;
        float h00 = cvt_tf32(a00), l00 = cvt_tf32(a00 - h00);
        float h10 = cvt_tf32(a10), l10 = cvt_tf32(a10 - h10);
        float h01 = cvt_tf32(a01), l01 = cvt_tf32(a01 - h01);
        float h11 = cvt_tf32(a11), l11 = cvt_tf32(a11 - h11);
        unsigned ah0 = __float_as_uint(h00), ah1 = __float_as_uint(h10);
        unsigned ah2 = __float_as_uint(h01), ah3 = __float_as_uint(h11);
        unsigned al0 = __float_as_uint(l00), al1 = __float_as_uint(l10);
        unsigned al2 = __float_as_uint(l01), al3 = __float_as_uint(l11);

#pragma unroll
        for (int nt = 0; nt < 8; nt++) {
            int n0 = nt * 8 + g;
            unsigned bh0 = __float_as_uint(sWhi[(k0 + tig)     * 72 + n0]);
            unsigned bh1 = __float_as_uint(sWhi[(k0 + tig + 4) * 72 + n0]);
            unsigned bl0 = __float_as_uint(sWlo[(k0 + tig)     * 72 + n0]);
            unsigned bl1 = __float_as_uint(sWlo[(k0 + tig + 4) * 72 + n0]);
            mma_tf32(C[nt], ah0, ah1, ah2, ah3, bh0, bh1);
            mma_tf32(C[nt], ah0, ah1, ah2, ah3, bl0, bl1);
            mma_tf32(C[nt], al0, al1, al2, al3, bh0, bh1);
        }
    }

    // Epilogue: store h16, accumulate a_s/a_d partials over this thread's cols
    float ps0 = 0.f, ps8 = 0.f, pd0 = 0.f, pd8 = 0.f;
#pragma unroll
    for (int nt = 0; nt < 8; nt++) {
        int col0 = nt * 8 + tig * 2;
        float s0 = __ldg(&att_src[col0]), s1 = __ldg(&att_src[col0 + 1]);
        float d0 = __ldg(&att_dst[col0]), d1 = __ldg(&att_dst[col0 + 1]);
        ps0 += C[nt][0] * s0 + C[nt][1] * s1;
        pd0 += C[nt][0] * d0 + C[nt][1] * d1;
        ps8 += C[nt][2] * s0 + C[nt][3] * s1;
        pd8 += C[nt][2] * d0 + C[nt][3] * d1;
        if (row0 < N)
            g_h16[row0 * 32 + nt * 4 + tig] = __floats2half2_rn(C[nt][0], C[nt][1]);
        if (row8 < N)
            g_h16[row8 * 32 + nt * 4 + tig] = __floats2half2_rn(C[nt][2], C[nt][3]);
    }
    // reduce across tig group (4 consecutive lanes)
#pragma unroll
    for (int o = 2; o; o >>= 1) {
        ps0 += __shfl_down_sync(0xffffffffu, ps0, o, 4);
        pd0 += __shfl_down_sync(0xffffffffu, pd0, o, 4);
        ps8 += __shfl_down_sync(0xffffffffu, ps8, o, 4);
        pd8 += __shfl_down_sync(0xffffffffu, pd8, o, 4);
    }
    if (tig == 0) {
        if (row0 < N) { g_as[row0] = ps0; g_ad[row0] = pd0; }
        if (row8 < N) { g_as[row8] = ps8; g_ad[row8] = pd8; }
    }

    // Fused dst histogram (grid-stride over all edges + self-loops)
    int T = E + N;
    for (int i = blockIdx.x * 256 + tid; i < T; i += gridDim.x * 256) {
        int d = (i < E) ? __ldg(&ei[E + i]) : (i - E);
        atomicAdd(&g_cnt[d], 1);
    }
}

// ---------------------------------------------------------------------------
// Scan stages
// ---------------------------------------------------------------------------
__device__ __forceinline__ int block_scan_1024(int v, int t, int* total) {
    int lane = t & 31, wid = t >> 5;
    int x = v;
#pragma unroll
    for (int o = 1; o < 32; o <<= 1) {
        int y = __shfl_up_sync(0xffffffffu, x, o);
        if (lane >= o) x += y;
    }
    __shared__ int ws[32];
    if (lane == 31) ws[wid] = x;
    __syncthreads();
    if (wid == 0) {
        int s = ws[lane];
#pragma unroll
        for (int o = 1; o < 32; o <<= 1) {
            int y = __shfl_up_sync(0xffffffffu, s, o);
            if (lane >= o) s += y;
        }
        ws[lane] = s;
    }
    __syncthreads();
    int add = wid ? ws[wid - 1] : 0;
    *total = ws[31];
    return x + add - v;
}

__global__ void k_scan1(int n) {
    int t = threadIdx.x;
    int i = blockIdx.x * 1024 + t;
    int v = (i < n) ? g_cnt[i] : 0;
    int total;
    int ex = block_scan_1024(v, t, &total);
    if (i < n) g_excl[i] = ex;
    if (t == 0) g_bsum[blockIdx.x] = total;
}

__global__ void k_scan2(int nb) {
    int t = threadIdx.x;
    int v = (t < nb) ? g_bsum[t] : 0;
    int total;
    int ex = block_scan_1024(v, t, &total);
    if (t < nb) g_boff[t] = ex;
}

__global__ void k_scan_add(int n) {
    int i = blockIdx.x * 1024 + threadIdx.x;
    if (i >= n) return;
    int v = g_excl[i] + g_boff[blockIdx.x];
    g_off[i] = v;
    g_cur[i] = v;
}

// ---------------------------------------------------------------------------
// Scatter: w = exp(leaky_relu(a_s[s]+a_d[d])) into dst-sorted position.
// ---------------------------------------------------------------------------
__global__ void k_scatter(const int* __restrict__ ei, int N, int E) {
    int i = blockIdx.x * blockDim.x + threadIdx.x;
    if (i >= E + N) return;
    int s, d;
    if (i < E) { s = ei[i]; d = ei[E + i]; }
    else       { s = d = i - E; }
    float e = g_as[s] + g_ad[d];
    e = (e > 0.0f) ? e : 0.2f * e;
    float w = __expf(e);
    int pos = atomicAdd(&g_cur[d], 1);
    g_swE[pos] = make_int2(s, __float_as_int(w));
}

// ---------------------------------------------------------------------------
// Gather (fp16 h) + normalize + bias + LayerNorm, fused. Half-warp per node.
// ---------------------------------------------------------------------------
__global__ void k_gather(const float* __restrict__ bias,
                         const float* __restrict__ gamma,
                         const float* __restrict__ beta,
                         float* __restrict__ out, int N) {
    int idx  = blockIdx.x * blockDim.x + threadIdx.x;
    int node = idx >> 4;
    int sub  = idx & 15;
    unsigned hm = 0xFFFFu << (threadIdx.x & 16);
    if (node >= N) return;

    int start = g_off[node];
    int deg   = g_cnt[node];

    float4 acc = make_float4(0.f, 0.f, 0.f, 0.f);
    float wsum = 0.0f;

    for (int base = 0; base < deg; base += 16) {
        int sj = 0; float wj = 0.0f;
        if (base + sub < deg) {
            int2 sw = g_swE[start + base + sub];
            sj = sw.x; wj = __int_as_float(sw.y);
        }
        int m = min(16, deg - base);
        for (int j = 0; j < m; j++) {
            int   s = __shfl_sync(hm, sj, j, 16);
            float w = __shfl_sync(hm, wj, j, 16);
            uint2 raw = *(const uint2*)&g_h16[s * 32 + sub * 2];
            float2 f0 = __half22float2(*(__half2*)&raw.x);
            float2 f1 = __half22float2(*(__half2*)&raw.y);
            acc.x = fmaf(w, f0.x, acc.x);
            acc.y = fmaf(w, f0.y, acc.y);
            acc.z = fmaf(w, f1.x, acc.z);
            acc.w = fmaf(w, f1.y, acc.w);
            wsum += w;
        }
    }

    float inv = 1.0f / wsum;
    float4 bv = *(const float4*)&bias[sub * 4];
    float v0 = acc.x * inv + bv.x;
    float v1 = acc.y * inv + bv.y;
    float v2 = acc.z * inv + bv.z;
    float v3 = acc.w * inv + bv.w;

    float sum = v0 + v1 + v2 + v3;
#pragma unroll
    for (int o = 8; o; o >>= 1) sum += __shfl_xor_sync(hm, sum, o, 16);
    float mu = sum * (1.0f / 64.0f);

    float d0 = v0 - mu, d1 = v1 - mu, d2 = v2 - mu, d3 = v3 - mu;
    float sq = d0*d0 + d1*d1 + d2*d2 + d3*d3;
#pragma unroll
    for (int o = 8; o; o >>= 1) sq += __shfl_xor_sync(hm, sq, o, 16);
    float rs = rsqrtf(sq * (1.0f / 64.0f) + 1e-5f);

    float4 gv = *(const float4*)&gamma[sub * 4];
    float4 be = *(const float4*)&beta[sub * 4];
    float4 o4;
    o4.x = d0 * rs * gv.x + be.x;
    o4.y = d1 * rs * gv.y + be.y;
    o4.z = d2 * rs * gv.z + be.z;
    o4.w = d3 * rs * gv.w + be.w;
    *(float4*)&out[node * 64 + sub * 4] = o4;
}

// ---------------------------------------------------------------------------
extern "C" void kernel_launch(void* const* d_in, const int* in_sizes, int n_in,
                              void* d_out, int out_size) {
    const float* x       = (const float*)d_in[0];
    const int*   ei      = (const int*)d_in[1];     // int32
    const float* W       = (const float*)d_in[2];
    const float* att_src = (const float*)d_in[3];
    const float* att_dst = (const float*)d_in[4];
    const float* bias    = (const float*)d_in[5];
    const float* gamma   = (const float*)d_in[6];
    const float* beta    = (const float*)d_in[7];
    float*       out     = (float*)d_out;

    int N = in_sizes[0] / DIM;
    int E = in_sizes[1] / 2;
    int T = E + N;
    int nScanBlocks = (N + 1023) / 1024;

    k_zero    <<<(N + 255) / 256, 256>>>(N);
    k_gemm    <<<(N + 127) / 128, 256>>>(x, W, att_src, att_dst, ei, N, E);
    k_scan1   <<<nScanBlocks, 1024>>>(N);
    k_scan2   <<<1, 1024>>>(nScanBlocks);
    k_scan_add<<<nScanBlocks, 1024>>>(N);
    k_scatter <<<(T + 255) / 256, 256>>>(ei, N, E);
    k_gather  <<<(N * 16 + 255) / 256, 256>>>(bias, gamma, beta, out, N);
}

// round 9
// speedup vs baseline: 1.9940x; 1.0706x over previous
#include <cuda_runtime.h>
#include <cuda_fp16.h>
#include <math.h>

#define DIM 64
#define N_MAX 100000
#define E_MAX 1200000
#define T_MAX (E_MAX + N_MAX)
#define NSCAN_MAX 128
#define FLAG_RDY 0x40000000

__device__ __half2 g_h16[N_MAX * 32];  // h = x @ W, fp16 (gather-only consumer)
__device__ float g_as[N_MAX];
__device__ float g_ad[N_MAX];
__device__ int   g_cnt[N_MAX];         // per-dst degree (zeroed by k_scan after use)
__device__ int   g_state[NSCAN_MAX];   // lookback state (zeroed by k_gemm blk 0)
__device__ int   g_off[N_MAX + 1];     // segment starts (+ total at [N])
__device__ int   g_cur[N_MAX];         // scatter cursor
__device__ int2  g_swE[T_MAX];         // dst-sorted (src, weight-bits)

// ---------------------------------------------------------------------------
// tf32 helpers
// ---------------------------------------------------------------------------
__device__ __forceinline__ float cvt_tf32(float x) {
    unsigned o;
    asm("cvt.rna.tf32.f32 %0, %1;" : "=r"(o) : "f"(x));
    return __uint_as_float(o);
}

__device__ __forceinline__ void mma_tf32(float c[4],
                                         unsigned a0, unsigned a1, unsigned a2, unsigned a3,
                                         unsigned b0, unsigned b1) {
    asm volatile(
        "mma.sync.aligned.m16n8k8.row.col.f32.tf32.tf32.f32 "
        "{%0,%1,%2,%3},{%4,%5,%6,%7},{%8,%9},{%0,%1,%2,%3};"
        : "+f"(c[0]), "+f"(c[1]), "+f"(c[2]), "+f"(c[3])
        : "r"(a0), "r"(a1), "r"(a2), "r"(a3), "r"(b0), "r"(b1));
}

// ---------------------------------------------------------------------------
// GEMM via 3xTF32 mma: h = x @ W (fp16 out), fused a_s/a_d dots,
// fused dst histogram tail, fused lookback-state zeroing (block 0).
// ---------------------------------------------------------------------------
__global__ void k_gemm(const float* __restrict__ x, const float* __restrict__ W,
                       const float* __restrict__ att_src,
                       const float* __restrict__ att_dst,
                       const int* __restrict__ ei, int N, int E) {
    __shared__ float sWhi[64 * 72];
    __shared__ float sWlo[64 * 72];

    int tid  = threadIdx.x;
    int w    = tid >> 5;
    int lane = tid & 31;
    int g    = lane >> 2;
    int tig  = lane & 3;
    int row0 = blockIdx.x * 128 + w * 16 + g;
    int row8 = row0 + 8;

    if (blockIdx.x == 0 && tid < NSCAN_MAX) g_state[tid] = 0;

    for (int i = tid; i < 64 * 64; i += 256) {
        int k = i >> 6, n = i & 63;
        float v  = W[i];
        float hi = cvt_tf32(v);
        sWhi[k * 72 + n] = hi;
        sWlo[k * 72 + n] = cvt_tf32(v - hi);
    }
    __syncthreads();

    float C[8][4] = {};

#pragma unroll
    for (int ks = 0; ks < 8; ks++) {
        int k0 = ks * 8;
        float a00 = (row0 < N) ? __ldg(&x[row0 * 64 + k0 + tig])     : 0.0f;
        float a10 = (row8 < N) ? __ldg(&x[row8 * 64 + k0 + tig])     : 0.0f;
        float a01 = (row0 < N) ? __ldg(&x[row0 * 64 + k0 + tig + 4]) : 0.0f;
        float a11 = (row8 < N) ? __ldg(&x[row8 * 64 + k0 + tig + 4]) : 0.0f;
        float h00 = cvt_tf32(a00), l00 = cvt_tf32(a00 - h00);
        float h10 = cvt_tf32(a10), l10 = cvt_tf32(a10 - h10);
        float h01 = cvt_tf32(a01), l01 = cvt_tf32(a01 - h01);
        float h11 = cvt_tf32(a11), l11 = cvt_tf32(a11 - h11);
        unsigned ah0 = __float_as_uint(h00), ah1 = __float_as_uint(h10);
        unsigned ah2 = __float_as_uint(h01), ah3 = __float_as_uint(h11);
        unsigned al0 = __float_as_uint(l00), al1 = __float_as_uint(l10);
        unsigned al2 = __float_as_uint(l01), al3 = __float_as_uint(l11);

#pragma unroll
        for (int nt = 0; nt < 8; nt++) {
            int n0 = nt * 8 + g;
            unsigned bh0 = __float_as_uint(sWhi[(k0 + tig)     * 72 + n0]);
            unsigned bh1 = __float_as_uint(sWhi[(k0 + tig + 4) * 72 + n0]);
            unsigned bl0 = __float_as_uint(sWlo[(k0 + tig)     * 72 + n0]);
            unsigned bl1 = __float_as_uint(sWlo[(k0 + tig + 4) * 72 + n0]);
            mma_tf32(C[nt], ah0, ah1, ah2, ah3, bh0, bh1);
            mma_tf32(C[nt], ah0, ah1, ah2, ah3, bl0, bl1);
            mma_tf32(C[nt], al0, al1, al2, al3, bh0, bh1);
        }
    }

    float ps0 = 0.f, ps8 = 0.f, pd0 = 0.f, pd8 = 0.f;
#pragma unroll
    for (int nt = 0; nt < 8; nt++) {
        int col0 = nt * 8 + tig * 2;
        float s0 = __ldg(&att_src[col0]), s1 = __ldg(&att_src[col0 + 1]);
        float d0 = __ldg(&att_dst[col0]), d1 = __ldg(&att_dst[col0 + 1]);
        ps0 += C[nt][0] * s0 + C[nt][1] * s1;
        pd0 += C[nt][0] * d0 + C[nt][1] * d1;
        ps8 += C[nt][2] * s0 + C[nt][3] * s1;
        pd8 += C[nt][2] * d0 + C[nt][3] * d1;
        if (row0 < N)
            g_h16[row0 * 32 + nt * 4 + tig] = __floats2half2_rn(C[nt][0], C[nt][1]);
        if (row8 < N)
            g_h16[row8 * 32 + nt * 4 + tig] = __floats2half2_rn(C[nt][2], C[nt][3]);
    }
#pragma unroll
    for (int o = 2; o; o >>= 1) {
        ps0 += __shfl_down_sync(0xffffffffu, ps0, o, 4);
        pd0 += __shfl_down_sync(0xffffffffu, pd0, o, 4);
        ps8 += __shfl_down_sync(0xffffffffu, ps8, o, 4);
        pd8 += __shfl_down_sync(0xffffffffu, pd8, o, 4);
    }
    if (tig == 0) {
        if (row0 < N) { g_as[row0] = ps0; g_ad[row0] = pd0; }
        if (row8 < N) { g_as[row8] = ps8; g_ad[row8] = pd8; }
    }

    // Fused dst histogram (grid-stride over edges + self-loops)
    int T = E + N;
    for (int i = blockIdx.x * 256 + tid; i < T; i += gridDim.x * 256) {
        int d = (i < E) ? __ldg(&ei[E + i]) : (i - E);
        atomicAdd(&g_cnt[d], 1);
    }
}

// ---------------------------------------------------------------------------
// Single-launch exclusive scan of g_cnt via aggregate lookback.
// All blocks co-resident (98 blocks < 148 SMs) -> polling is safe.
// Also: writes g_off[N] = total, re-zeros g_cnt for the next replay.
// ---------------------------------------------------------------------------
__device__ __forceinline__ int block_scan_1024(int v, int t, int* total) {
    int lane = t & 31, wid = t >> 5;
    int x = v;
#pragma unroll
    for (int o = 1; o < 32; o <<= 1) {
        int y = __shfl_up_sync(0xffffffffu, x, o);
        if (lane >= o) x += y;
    }
    __shared__ int ws[32];
    if (lane == 31) ws[wid] = x;
    __syncthreads();
    if (wid == 0) {
        int s = ws[lane];
#pragma unroll
        for (int o = 1; o < 32; o <<= 1) {
            int y = __shfl_up_sync(0xffffffffu, s, o);
            if (lane >= o) s += y;
        }
        ws[lane] = s;
    }
    __syncthreads();
    int add = wid ? ws[wid - 1] : 0;
    *total = ws[31];
    return x + add - v;
}

__global__ void k_scan(int n) {
    int t = threadIdx.x;
    int b = blockIdx.x;
    int i = b * 1024 + t;
    int v = (i < n) ? g_cnt[i] : 0;
    int total;
    int ex = block_scan_1024(v, t, &total);

    if (t == 0) atomicExch(&g_state[b], FLAG_RDY | total);

    __shared__ int s_prefix;
    if (t < 32) {
        int sum = 0;
        for (int base = 0; base < b; base += 32) {
            int p = base + t;
            if (p < b) {
                int val;
                do { val = *(volatile int*)&g_state[p]; } while (!(val & FLAG_RDY));
                sum += val & (FLAG_RDY - 1);
            }
        }
#pragma unroll
        for (int o = 16; o; o >>= 1) sum += __shfl_xor_sync(0xffffffffu, sum, o);
        if (t == 0) s_prefix = sum;
    }
    __syncthreads();

    int off = s_prefix + ex;
    if (i < n) {
        g_off[i] = off;
        g_cur[i] = off;
        g_cnt[i] = 0;          // reset for next replay
    }
    if (i == n - 1) g_off[n] = off + v;
}

// ---------------------------------------------------------------------------
// Scatter: w = exp(leaky_relu(a_s[s]+a_d[d])) into dst-sorted position.
// ---------------------------------------------------------------------------
__global__ void k_scatter(const int* __restrict__ ei, int N, int E) {
    int i = blockIdx.x * blockDim.x + threadIdx.x;
    if (i >= E + N) return;
    int s, d;
    if (i < E) { s = ei[i]; d = ei[E + i]; }
    else       { s = d = i - E; }
    float e = g_as[s] + g_ad[d];
    e = (e > 0.0f) ? e : 0.2f * e;
    float w = __expf(e);
    int pos = atomicAdd(&g_cur[d], 1);
    g_swE[pos] = make_int2(s, __float_as_int(w));
}

// ---------------------------------------------------------------------------
// Gather (fp16 h) + normalize + bias + LayerNorm, fused. Half-warp per node.
// deg from off[i+1]-off[i].
// ---------------------------------------------------------------------------
__global__ void k_gather(const float* __restrict__ bias,
                         const float* __restrict__ gamma,
                         const float* __restrict__ beta,
                         float* __restrict__ out, int N) {
    int idx  = blockIdx.x * blockDim.x + threadIdx.x;
    int node = idx >> 4;
    int sub  = idx & 15;
    unsigned hm = 0xFFFFu << (threadIdx.x & 16);
    if (node >= N) return;

    int start = g_off[node];
    int deg   = g_off[node + 1] - start;

    float4 acc = make_float4(0.f, 0.f, 0.f, 0.f);
    float wsum = 0.0f;

    for (int base = 0; base < deg; base += 16) {
        int sj = 0; float wj = 0.0f;
        if (base + sub < deg) {
            int2 sw = g_swE[start + base + sub];
            sj = sw.x; wj = __int_as_float(sw.y);
        }
        int m = min(16, deg - base);
        for (int j = 0; j < m; j++) {
            int   s = __shfl_sync(hm, sj, j, 16);
            float w = __shfl_sync(hm, wj, j, 16);
            uint2 raw = *(const uint2*)&g_h16[s * 32 + sub * 2];
            float2 f0 = __half22float2(*(__half2*)&raw.x);
            float2 f1 = __half22float2(*(__half2*)&raw.y);
            acc.x = fmaf(w, f0.x, acc.x);
            acc.y = fmaf(w, f0.y, acc.y);
            acc.z = fmaf(w, f1.x, acc.z);
            acc.w = fmaf(w, f1.y, acc.w);
            wsum += w;
        }
    }

    float inv = 1.0f / wsum;
    float4 bv = *(const float4*)&bias[sub * 4];
    float v0 = acc.x * inv + bv.x;
    float v1 = acc.y * inv + bv.y;
    float v2 = acc.z * inv + bv.z;
    float v3 = acc.w * inv + bv.w;

    float sum = v0 + v1 + v2 + v3;
#pragma unroll
    for (int o = 8; o; o >>= 1) sum += __shfl_xor_sync(hm, sum, o, 16);
    float mu = sum * (1.0f / 64.0f);

    float d0 = v0 - mu, d1 = v1 - mu, d2 = v2 - mu, d3 = v3 - mu;
    float sq = d0*d0 + d1*d1 + d2*d2 + d3*d3;
#pragma unroll
    for (int o = 8; o; o >>= 1) sq += __shfl_xor_sync(hm, sq, o, 16);
    float rs = rsqrtf(sq * (1.0f / 64.0f) + 1e-5f);

    float4 gv = *(const float4*)&gamma[sub * 4];
    float4 be = *(const float4*)&beta[sub * 4];
    float4 o4;
    o4.x = d0 * rs * gv.x + be.x;
    o4.y = d1 * rs * gv.y + be.y;
    o4.z = d2 * rs * gv.z + be.z;
    o4.w = d3 * rs * gv.w + be.w;
    *(float4*)&out[node * 64 + sub * 4] = o4;
}

// ---------------------------------------------------------------------------
extern "C" void kernel_launch(void* const* d_in, const int* in_sizes, int n_in,
                              void* d_out, int out_size) {
    const float* x       = (const float*)d_in[0];
    const int*   ei      = (const int*)d_in[1];     // int32
    const float* W       = (const float*)d_in[2];
    const float* att_src = (const float*)d_in[3];
    const float* att_dst = (const float*)d_in[4];
    const float* bias    = (const float*)d_in[5];
    const float* gamma   = (const float*)d_in[6];
    const float* beta    = (const float*)d_in[7];
    float*       out     = (float*)d_out;

    int N = in_sizes[0] / DIM;
    int E = in_sizes[1] / 2;
    int T = E + N;
    int nScanBlocks = (N + 1023) / 1024;   // 98 <= NSCAN_MAX, all co-resident

    k_gemm   <<<(N + 127) / 128, 256>>>(x, W, att_src, att_dst, ei, N, E);
    k_scan   <<<nScanBlocks, 1024>>>(N);
    k_scatter<<<(T + 255) / 256, 256>>>(ei, N, E);
    k_gather <<<(N * 16 + 255) / 256, 256>>>(bias, gamma, beta, out, N);
}

// round 11
// speedup vs baseline: 2.0265x; 1.0163x over previous
#include <cuda_runtime.h>
#include <cuda_fp16.h>
#include <math.h>

#define DIM 64
#define N_MAX 100000
#define E_MAX 1200000
#define T_MAX (E_MAX + N_MAX)
#define NSCAN_MAX 128
#define FLAG_RDY 0x40000000

// dynamic smem partition sizes (floats)
#define SW_ELEMS (64 * 72)
#define SX_ELEMS (128 * 68)
#define GEMM_SMEM_BYTES ((2 * SW_ELEMS + SX_ELEMS) * 4)

__device__ __half2 g_h16[N_MAX * 32];  // h = x @ W, fp16 (gather-only consumer)
__device__ float g_as[N_MAX];
__device__ float g_ad[N_MAX];
__device__ int   g_cnt[N_MAX];         // per-dst degree (zeroed by k_scan after use)
__device__ int   g_state[NSCAN_MAX];   // lookback state (zeroed by k_gemm blk 0)
__device__ int   g_off[N_MAX + 1];     // segment starts (+ total at [N])
__device__ int   g_cur[N_MAX];         // scatter cursor
__device__ int2  g_swE[T_MAX];         // dst-sorted (src, weight-bits)

// ---------------------------------------------------------------------------
// helpers: tf32 + packed f32x2
// ---------------------------------------------------------------------------
__device__ __forceinline__ float cvt_tf32(float x) {
    unsigned o;
    asm("cvt.rna.tf32.f32 %0, %1;" : "=r"(o) : "f"(x));
    return __uint_as_float(o);
}

__device__ __forceinline__ void mma_tf32(float c[4],
                                         unsigned a0, unsigned a1, unsigned a2, unsigned a3,
                                         unsigned b0, unsigned b1) {
    asm volatile(
        "mma.sync.aligned.m16n8k8.row.col.f32.tf32.tf32.f32 "
        "{%0,%1,%2,%3},{%4,%5,%6,%7},{%8,%9},{%0,%1,%2,%3};"
        : "+f"(c[0]), "+f"(c[1]), "+f"(c[2]), "+f"(c[3])
        : "r"(a0), "r"(a1), "r"(a2), "r"(a3), "r"(b0), "r"(b1));
}

__device__ __forceinline__ unsigned long long pk2(float x, float y) {
    unsigned long long r;
    asm("mov.b64 %0, {%1,%2};" : "=l"(r) : "f"(x), "f"(y));
    return r;
}
__device__ __forceinline__ void fma2(unsigned long long& c,
                                     unsigned long long a, unsigned long long b) {
    asm("fma.rn.f32x2 %0, %1, %2, %0;" : "+l"(c) : "l"(a), "l"(b));
}
__device__ __forceinline__ float2 upk2(unsigned long long v) {
    float x, y;
    asm("mov.b64 {%0,%1}, %2;" : "=f"(x), "=f"(y) : "l"(v));
    return make_float2(x, y);
}

// ---------------------------------------------------------------------------
// GEMM via 3xTF32 mma: h = x @ W (fp16 out), fused a_s/a_d dots, fused
// dst histogram, fused lookback-state zeroing. A staged via dynamic smem.
// Block: 256 threads (8 warps), 128 rows.
// ---------------------------------------------------------------------------
__global__ void k_gemm(const float* __restrict__ x, const float* __restrict__ W,
                       const float* __restrict__ att_src,
                       const float* __restrict__ att_dst,
                       const int* __restrict__ ei, int N, int E) {
    extern __shared__ float smem[];
    float* sWhi = smem;
    float* sWlo = smem + SW_ELEMS;
    float* sX   = smem + 2 * SW_ELEMS;   // stride 68: conflict-free frag reads

    int tid  = threadIdx.x;
    int w    = tid >> 5;
    int lane = tid & 31;
    int g    = lane >> 2;
    int tig  = lane & 3;
    int rb0  = blockIdx.x * 128;
    int row0 = rb0 + w * 16 + g;
    int row8 = row0 + 8;

    if (blockIdx.x == 0 && tid < NSCAN_MAX) g_state[tid] = 0;

    for (int i = tid; i < 64 * 64; i += 256) {
        int k = i >> 6, n = i & 63;
        float v  = W[i];
        float hi = cvt_tf32(v);
        sWhi[k * 72 + n] = hi;
        sWlo[k * 72 + n] = cvt_tf32(v - hi);
    }
    // coalesced float4 staging of x tile (128 rows x 64 cols)
    for (int i = tid; i < 128 * 16; i += 256) {
        int r = i >> 4, c4 = i & 15;
        float4 v = (rb0 + r < N) ? *(const float4*)&x[(rb0 + r) * 64 + c4 * 4]
                                 : make_float4(0.f, 0.f, 0.f, 0.f);
        *(float4*)&sX[r * 68 + c4 * 4] = v;
    }
    __syncthreads();

    int lr0 = w * 16 + g;     // local rows
    int lr8 = lr0 + 8;
    float C[8][4] = {};

#pragma unroll
    for (int ks = 0; ks < 8; ks++) {
        int k0 = ks * 8;
        float a00 = sX[lr0 * 68 + k0 + tig];
        float a10 = sX[lr8 * 68 + k0 + tig];
        float a01 = sX[lr0 * 68 + k0 + tig + 4];
        float a11 = sX[lr8 * 68 + k0 + tig + 4];
        float h00 = cvt_tf32(a00), l00 = cvt_tf32(a00 - h00);
        float h10 = cvt_tf32(a10), l10 = cvt_tf32(a10 - h10);
        float h01 = cvt_tf32(a01), l01 = cvt_tf32(a01 - h01);
        float h11 = cvt_tf32(a11), l11 = cvt_tf32(a11 - h11);
        unsigned ah0 = __float_as_uint(h00), ah1 = __float_as_uint(h10);
        unsigned ah2 = __float_as_uint(h01), ah3 = __float_as_uint(h11);
        unsigned al0 = __float_as_uint(l00), al1 = __float_as_uint(l10);
        unsigned al2 = __float_as_uint(l01), al3 = __float_as_uint(l11);

#pragma unroll
        for (int nt = 0; nt < 8; nt++) {
            int n0 = nt * 8 + g;
            unsigned bh0 = __float_as_uint(sWhi[(k0 + tig)     * 72 + n0]);
            unsigned bh1 = __float_as_uint(sWhi[(k0 + tig + 4) * 72 + n0]);
            unsigned bl0 = __float_as_uint(sWlo[(k0 + tig)     * 72 + n0]);
            unsigned bl1 = __float_as_uint(sWlo[(k0 + tig + 4) * 72 + n0]);
            mma_tf32(C[nt], ah0, ah1, ah2, ah3, bh0, bh1);
            mma_tf32(C[nt], ah0, ah1, ah2, ah3, bl0, bl1);
            mma_tf32(C[nt], al0, al1, al2, al3, bh0, bh1);
        }
    }

    float ps0 = 0.f, ps8 = 0.f, pd0 = 0.f, pd8 = 0.f;
#pragma unroll
    for (int nt = 0; nt < 8; nt++) {
        int col0 = nt * 8 + tig * 2;
        float s0 = __ldg(&att_src[col0]), s1 = __ldg(&att_src[col0 + 1]);
        float d0 = __ldg(&att_dst[col0]), d1 = __ldg(&att_dst[col0 + 1]);
        ps0 += C[nt][0] * s0 + C[nt][1] * s1;
        pd0 += C[nt][0] * d0 + C[nt][1] * d1;
        ps8 += C[nt][2] * s0 + C[nt][3] * s1;
        pd8 += C[nt][2] * d0 + C[nt][3] * d1;
        if (row0 < N)
            g_h16[row0 * 32 + nt * 4 + tig] = __floats2half2_rn(C[nt][0], C[nt][1]);
        if (row8 < N)
            g_h16[row8 * 32 + nt * 4 + tig] = __floats2half2_rn(C[nt][2], C[nt][3]);
    }
#pragma unroll
    for (int o = 2; o; o >>= 1) {
        ps0 += __shfl_down_sync(0xffffffffu, ps0, o, 4);
        pd0 += __shfl_down_sync(0xffffffffu, pd0, o, 4);
        ps8 += __shfl_down_sync(0xffffffffu, ps8, o, 4);
        pd8 += __shfl_down_sync(0xffffffffu, pd8, o, 4);
    }
    if (tig == 0) {
        if (row0 < N) { g_as[row0] = ps0; g_ad[row0] = pd0; }
        if (row8 < N) { g_as[row8] = ps8; g_ad[row8] = pd8; }
    }

    // fused dst histogram
    int T = E + N;
    for (int i = blockIdx.x * 256 + tid; i < T; i += gridDim.x * 256) {
        int d = (i < E) ? __ldg(&ei[E + i]) : (i - E);
        atomicAdd(&g_cnt[d], 1);
    }
}

// ---------------------------------------------------------------------------
// Single-launch exclusive scan via aggregate lookback (98 co-resident blocks).
// Writes off[N]=total, re-zeros g_cnt.
// ---------------------------------------------------------------------------
__device__ __forceinline__ int block_scan_1024(int v, int t, int* total) {
    int lane = t & 31, wid = t >> 5;
    int x = v;
#pragma unroll
    for (int o = 1; o < 32; o <<= 1) {
        int y = __shfl_up_sync(0xffffffffu, x, o);
        if (lane >= o) x += y;
    }
    __shared__ int ws[32];
    if (lane == 31) ws[wid] = x;
    __syncthreads();
    if (wid == 0) {
        int s = ws[lane];
#pragma unroll
        for (int o = 1; o < 32; o <<= 1) {
            int y = __shfl_up_sync(0xffffffffu, s, o);
            if (lane >= o) s += y;
        }
        ws[lane] = s;
    }
    __syncthreads();
    int add = wid ? ws[wid - 1] : 0;
    *total = ws[31];
    return x + add - v;
}

__global__ void k_scan(int n) {
    int t = threadIdx.x;
    int b = blockIdx.x;
    int i = b * 1024 + t;
    int v = (i < n) ? g_cnt[i] : 0;
    int total;
    int ex = block_scan_1024(v, t, &total);

    if (t == 0) atomicExch(&g_state[b], FLAG_RDY | total);

    __shared__ int s_prefix;
    if (t < 32) {
        int sum = 0;
        for (int base = 0; base < b; base += 32) {
            int p = base + t;
            if (p < b) {
                int val;
                do { val = *(volatile int*)&g_state[p]; } while (!(val & FLAG_RDY));
                sum += val & (FLAG_RDY - 1);
            }
        }
#pragma unroll
        for (int o = 16; o; o >>= 1) sum += __shfl_xor_sync(0xffffffffu, sum, o);
        if (t == 0) s_prefix = sum;
    }
    __syncthreads();

    int off = s_prefix + ex;
    if (i < n) {
        g_off[i] = off;
        g_cur[i] = off;
        g_cnt[i] = 0;
    }
    if (i == n - 1) g_off[n] = off + v;
}

// ---------------------------------------------------------------------------
// Scatter: w = exp(leaky_relu(a_s[s]+a_d[d])) into dst-sorted position.
// ---------------------------------------------------------------------------
__global__ void k_scatter(const int* __restrict__ ei, int N, int E) {
    int i = blockIdx.x * blockDim.x + threadIdx.x;
    if (i >= E + N) return;
    int s, d;
    if (i < E) { s = ei[i]; d = ei[E + i]; }
    else       { s = d = i - E; }
    float e = g_as[s] + g_ad[d];
    e = (e > 0.0f) ? e : 0.2f * e;
    float w = __expf(e);
    int pos = atomicAdd(&g_cur[d], 1);
    g_swE[pos] = make_int2(s, __float_as_int(w));
}

// ---------------------------------------------------------------------------
// Gather (fp16 h) + normalize + bias + LayerNorm. Half-warp per node.
// 2-edge unrolled, packed fma.rn.f32x2 accumulate.
// ---------------------------------------------------------------------------
__global__ void k_gather(const float* __restrict__ bias,
                         const float* __restrict__ gamma,
                         const float* __restrict__ beta,
                         float* __restrict__ out, int N) {
    int idx  = blockIdx.x * blockDim.x + threadIdx.x;
    int node = idx >> 4;
    int sub  = idx & 15;
    unsigned hm = 0xFFFFu << (threadIdx.x & 16);
    if (node >= N) return;

    int start = g_off[node];
    int deg   = g_off[node + 1] - start;

    unsigned long long acc01 = 0ull, acc23 = 0ull;   // packed {0.f,0.f}
    float wsum = 0.0f;

    for (int base = 0; base < deg; base += 16) {
        int sj = 0; float wj = 0.0f;
        if (base + sub < deg) {
            int2 sw = g_swE[start + base + sub];
            sj = sw.x; wj = __int_as_float(sw.y);
        }
        int m = min(16, deg - base);
        int j = 0;
        for (; j + 2 <= m; j += 2) {
            int   s0 = __shfl_sync(hm, sj, j,     16);
            float w0 = __shfl_sync(hm, wj, j,     16);
            int   s1 = __shfl_sync(hm, sj, j + 1, 16);
            float w1 = __shfl_sync(hm, wj, j + 1, 16);
            uint2 r0 = *(const uint2*)&g_h16[s0 * 32 + sub * 2];
            uint2 r1 = *(const uint2*)&g_h16[s1 * 32 + sub * 2];
            float2 a0 = __half22float2(*(__half2*)&r0.x);
            float2 b0 = __half22float2(*(__half2*)&r0.y);
            float2 a1 = __half22float2(*(__half2*)&r1.x);
            float2 b1 = __half22float2(*(__half2*)&r1.y);
            unsigned long long w0p = pk2(w0, w0);
            unsigned long long w1p = pk2(w1, w1);
            fma2(acc01, pk2(a0.x, a0.y), w0p);
            fma2(acc23, pk2(b0.x, b0.y), w0p);
            fma2(acc01, pk2(a1.x, a1.y), w1p);
            fma2(acc23, pk2(b1.x, b1.y), w1p);
            wsum += w0 + w1;
        }
        if (j < m) {
            int   s0 = __shfl_sync(hm, sj, j, 16);
            float w0 = __shfl_sync(hm, wj, j, 16);
            uint2 r0 = *(const uint2*)&g_h16[s0 * 32 + sub * 2];
            float2 a0 = __half22float2(*(__half2*)&r0.x);
            float2 b0 = __half22float2(*(__half2*)&r0.y);
            unsigned long long w0p = pk2(w0, w0);
            fma2(acc01, pk2(a0.x, a0.y), w0p);
            fma2(acc23, pk2(b0.x, b0.y), w0p);
            wsum += w0;
        }
    }

    float2 v01 = upk2(acc01);
    float2 v23 = upk2(acc23);

    float inv = 1.0f / wsum;
    float4 bv = *(const float4*)&bias[sub * 4];
    float v0 = v01.x * inv + bv.x;
    float v1 = v01.y * inv + bv.y;
    float v2 = v23.x * inv + bv.z;
    float v3 = v23.y * inv + bv.w;

    float sum = v0 + v1 + v2 + v3;
#pragma unroll
    for (int o = 8; o; o >>= 1) sum += __shfl_xor_sync(hm, sum, o, 16);
    float mu = sum * (1.0f / 64.0f);

    float d0 = v0 - mu, d1 = v1 - mu, d2 = v2 - mu, d3 = v3 - mu;
    float sq = d0*d0 + d1*d1 + d2*d2 + d3*d3;
#pragma unroll
    for (int o = 8; o; o >>= 1) sq += __shfl_xor_sync(hm, sq, o, 16);
    float rs = rsqrtf(sq * (1.0f / 64.0f) + 1e-5f);

    float4 gv = *(const float4*)&gamma[sub * 4];
    float4 be = *(const float4*)&beta[sub * 4];
    float4 o4;
    o4.x = d0 * rs * gv.x + be.x;
    o4.y = d1 * rs * gv.y + be.y;
    o4.z = d2 * rs * gv.z + be.z;
    o4.w = d3 * rs * gv.w + be.w;
    *(float4*)&out[node * 64 + sub * 4] = o4;
}

// ---------------------------------------------------------------------------
extern "C" void kernel_launch(void* const* d_in, const int* in_sizes, int n_in,
                              void* d_out, int out_size) {
    const float* x       = (const float*)d_in[0];
    const int*   ei      = (const int*)d_in[1];     // int32
    const float* W       = (const float*)d_in[2];
    const float* att_src = (const float*)d_in[3];
    const float* att_dst = (const float*)d_in[4];
    const float* bias    = (const float*)d_in[5];
    const float* gamma   = (const float*)d_in[6];
    const float* beta    = (const float*)d_in[7];
    float*       out     = (float*)d_out;

    int N = in_sizes[0] / DIM;
    int E = in_sizes[1] / 2;
    int T = E + N;
    int nScanBlocks = (N + 1023) / 1024;

    cudaFuncSetAttribute(k_gemm, cudaFuncAttributeMaxDynamicSharedMemorySize,
                         GEMM_SMEM_BYTES);

    k_gemm   <<<(N + 127) / 128, 256, GEMM_SMEM_BYTES>>>(x, W, att_src, att_dst, ei, N, E);
    k_scan   <<<nScanBlocks, 1024>>>(N);
    k_scatter<<<(T + 255) / 256, 256>>>(ei, N, E);
    k_gather <<<(N * 16 + 255) / 256, 256>>>(bias, gamma, beta, out, N);
}